// round 15
// baseline (speedup 1.0000x reference)
#include <cuda_runtime.h>

#define B_N   4096
#define S_N   5
#define D_N   64
#define HS_N  961
#define VSA_N 1024
#define LN_EPSF 1e-3f
#define KPAD 72
#define KTOT 1096   // 8 * 137
#define MDIM 137

#define GROUPS 8
#define TPB    1024

// dynamic smem layout (bytes)
#define OFF_HP   0                       // ull[5*1096]  = 43840  (pair table, shared)
#define OFF_VP   43840                   // float[8][5120] = 163840
#define OFF_XD   207680                  // ull[8][320]  = 20480
#define OFF_AUX  228160                  // 8 * 512
#define AUX_STRIDE 512
#define SMEM_DYN (OFF_AUX + GROUPS * AUX_STRIDE)   // 232256  (<= 227 KB)

typedef unsigned long long ull;

__device__ float g_sp[S_N * VSA_N];               // batch-invariant sp rows
__device__ __align__(16) ull g_hp[S_N * KTOT];    // strided PAIR table:
// g_hp[i*KTOT + (K&7)*MDIM + (K>>3)] = (lo=hpad[K-1], hi=hpad[K]),
// hpad[K] = (KPAD <= K < KPAD+HS_N) ? h[i][K-KPAD] : 0

// ---- packed f32x2 primitives (sm_103a) ----
#define PACK2(dst, lo, hi) \
    asm("mov.b64 %0, {%1, %2};" : "=l"(dst) : "f"(lo), "f"(hi))
#define FMA2(acc, a, b) \
    asm("fma.rn.f32x2 %0, %1, %2, %0;" : "+l"(acc) : "l"(a), "l"(b))
#define UNPACK2(lo, hi, src) \
    asm("mov.b64 {%0, %1}, %2;" : "=f"(lo), "=f"(hi) : "l"(src))

// group barrier: 128 threads of group g, named barrier id g+1
#define GBAR() asm volatile("bar.sync %0, %1;" :: "r"(g + 1), "r"(128) : "memory")

__device__ __forceinline__ float fast_silu(float x) {
    return x / (1.0f + __expf(-x));
}

// conv for 8 consecutive outputs t0..t0+7 (t0 = 8*wg_tid).
// Ring/slot/FMA structure VERBATIM R2; pw[s] now arrives as one LDS.64 from the
// pair table (address s*MDIM + c from base hp = table + (129 - wg_tid), which is
// algebraically identical to R2's l_d address for the pair (l_{d-1}, l_d)).
// xd[d] = (x_d, x_d) broadcast pairs in smem.
__device__ __forceinline__ void conv_pair(const ull* __restrict__ hpair,
                                          const ull* __restrict__ xd,
                                          int wg_tid, float acc[8]) {
    const ull* hp = hpair + (129 - wg_tid);
    ull acc2[4] = {0ull, 0ull, 0ull, 0ull};
    ull pw[8];
    // prime slots 2..7 with pairs at d = -6..-1: K = Kb + d -> hp[j*MDIM - 1]
    #pragma unroll
    for (int j = 2; j < 8; ++j) pw[j] = hp[j * MDIM - 1];
    #pragma unroll 2
    for (int c = 0; c < 8; ++c) {
        #pragma unroll
        for (int s = 0; s < 8; ++s) {
            pw[s] = hp[s * MDIM + c];          // pair (l_{d-1}, l_d), d = 8c+s
            ull xx = xd[(c << 3) + s];         // (x_d, x_d)
            FMA2(acc2[0], xx, pw[s]);          // acc[1],acc[0]
            FMA2(acc2[1], xx, pw[(s + 6) & 7]); // acc[3],acc[2]
            FMA2(acc2[2], xx, pw[(s + 4) & 7]); // acc[5],acc[4]
            FMA2(acc2[3], xx, pw[(s + 2) & 7]); // acc[7],acc[6]
        }
    }
    #pragma unroll
    for (int p = 0; p < 4; ++p) UNPACK2(acc[2 * p + 1], acc[2 * p], acc2[p]);
}

// ---------------- kernel 0: build g_hp + sp rows (one block per i) ----------------
__global__ __launch_bounds__(128)
void sp_kernel(const float* __restrict__ h,
               const float* __restrict__ symbols,
               const float* __restrict__ gamma,
               const float* __restrict__ beta) {
    __shared__ __align__(16) ull sh_hp[KTOT];
    __shared__ __align__(16) ull sh_xd[D_N];
    __shared__ float sh_red[8];
    __shared__ float sh_stats[2];

    const int tid  = threadIdx.x;
    const int lane = tid & 31;
    const int warp = tid >> 5;
    const int i    = blockIdx.x;
    const float* hrow = h + i * HS_N;

    for (int K = tid; K < KTOT; K += 128) {
        const float hi = (K >= KPAD && K < KPAD + HS_N) ? hrow[K - KPAD] : 0.f;
        const float lo = (K - 1 >= KPAD && K - 1 < KPAD + HS_N) ? hrow[K - 1 - KPAD] : 0.f;
        ull pr;
        PACK2(pr, lo, hi);
        const int a = (K & 7) * MDIM + (K >> 3);
        sh_hp[a] = pr;
        g_hp[i * KTOT + a] = pr;
    }
    if (tid < D_N) {
        unsigned u = __float_as_uint(symbols[i * D_N + tid]);
        sh_xd[tid] = ((ull)u << 32) | (ull)u;
    }
    __syncthreads();

    float acc[8];
    conv_pair(sh_hp, sh_xd, tid, acc);

    float y[8];
    float s1 = 0.f, s2 = 0.f;
    #pragma unroll
    for (int r = 0; r < 8; ++r) {
        float u = fast_silu(acc[r]);
        y[r] = u; s1 += u; s2 += u * u;
    }
    #pragma unroll
    for (int o = 16; o > 0; o >>= 1) {
        s1 += __shfl_xor_sync(0xffffffffu, s1, o);
        s2 += __shfl_xor_sync(0xffffffffu, s2, o);
    }
    if (lane == 0) { sh_red[warp] = s1; sh_red[4 + warp] = s2; }
    __syncthreads();
    if (tid == 0) {
        float a = sh_red[0] + sh_red[1] + sh_red[2] + sh_red[3];
        float q = sh_red[4] + sh_red[5] + sh_red[6] + sh_red[7];
        float mu = a * (1.f / VSA_N);
        float var = q * (1.f / VSA_N) - mu * mu;
        sh_stats[0] = mu;
        sh_stats[1] = rsqrtf(var + LN_EPSF);
    }
    __syncthreads();
    float mu = sh_stats[0], rs = sh_stats[1];
    const int t0 = tid << 3;
    #pragma unroll
    for (int r = 0; r < 8; ++r) {
        const int t = t0 + r;
        g_sp[i * VSA_N + t] = fmaf((y[r] - mu) * rs, gamma[t], beta[t]);
    }
}

// ---------------- main fused kernel: 8 batch groups per 1024-thread block ----------------
__global__ __launch_bounds__(TPB, 1)
void fused_main(const float* __restrict__ values,
                const float* __restrict__ gamma,
                const float* __restrict__ beta,
                float* __restrict__ out) {
    extern __shared__ __align__(16) char dynsm[];

    const int tid    = threadIdx.x;
    const int g      = tid >> 7;          // group 0..7
    const int wg_tid = tid & 127;         // tid within group
    const int lane   = tid & 31;
    const int warp   = (tid >> 5) & 3;    // warp within group
    const int b      = blockIdx.x * GROUPS + g;
    const int t0     = wg_tid << 3;

    ull*   sh_hp    = (ull*)(dynsm + OFF_HP);                         // shared by all groups
    float* sh_vp    = (float*)(dynsm + OFF_VP) + g * (S_N * VSA_N);
    ull*   sh_xd    = (ull*)(dynsm + OFF_XD) + g * (S_N * D_N);
    char*  auxp     = dynsm + OFF_AUX + g * AUX_STRIDE;
    int*   sh_negw  = (int*)auxp;              // [0,400)   scores phase
    float* sh_red   = (float*)(auxp + 400);    // [400,432) LN phase
    float* sh_stats = (float*)(auxp + 432);    // [432,440) LN phase
    float* sh_w     = (float*)(auxp + 400);    // [400,500) softmax/att phase (overlays red/stats — disjoint phases)

    // cooperative h-pair table load (all 1024 threads)
    {
        const float4* src = reinterpret_cast<const float4*>(g_hp);
        float4* dst = reinterpret_cast<float4*>(sh_hp);
        #pragma unroll 1
        for (int idx = tid; idx < (S_N * KTOT) / 2; idx += TPB) dst[idx] = src[idx];
    }
    // per-group x dup pairs from global values
    {
        const float* vb = values + (size_t)b * (S_N * D_N);
        #pragma unroll 1
        for (int idx = wg_tid; idx < S_N * D_N; idx += 128) {
            unsigned u = __float_as_uint(vb[idx]);
            sh_xd[idx] = ((ull)u << 32) | (ull)u;
        }
    }
    __syncthreads();   // only block-wide barrier; groups independent after this

    // ---- conv + silu + LayerNorm per i -> sh_vp ----
    #pragma unroll 1
    for (int i = 0; i < S_N; ++i) {
        float acc[8];
        conv_pair(sh_hp + i * KTOT, sh_xd + i * D_N, wg_tid, acc);

        float y[8];
        float s1 = 0.f, s2 = 0.f;
        #pragma unroll
        for (int r = 0; r < 8; ++r) {
            float u = fast_silu(acc[r]);
            y[r] = u; s1 += u; s2 += u * u;
        }
        #pragma unroll
        for (int o = 16; o > 0; o >>= 1) {
            s1 += __shfl_xor_sync(0xffffffffu, s1, o);
            s2 += __shfl_xor_sync(0xffffffffu, s2, o);
        }
        if (lane == 0) { sh_red[warp] = s1; sh_red[4 + warp] = s2; }
        GBAR();
        if (wg_tid == 0) {
            float a = sh_red[0] + sh_red[1] + sh_red[2] + sh_red[3];
            float q = sh_red[4] + sh_red[5] + sh_red[6] + sh_red[7];
            float mu = a * (1.f / VSA_N);
            float var = q * (1.f / VSA_N) - mu * mu;
            sh_stats[0] = mu;
            sh_stats[1] = rsqrtf(var + LN_EPSF);
        }
        GBAR();
        float mu = sh_stats[0], rs = sh_stats[1];

        float4 g0  = *reinterpret_cast<const float4*>(gamma + t0);
        float4 g1  = *reinterpret_cast<const float4*>(gamma + t0 + 4);
        float4 be0 = *reinterpret_cast<const float4*>(beta + t0);
        float4 be1 = *reinterpret_cast<const float4*>(beta + t0 + 4);
        float gg[8] = {g0.x, g0.y, g0.z, g0.w, g1.x, g1.y, g1.z, g1.w};
        float bb[8] = {be0.x, be0.y, be0.z, be0.w, be1.x, be1.y, be1.z, be1.w};
        float vv[8];
        #pragma unroll
        for (int r = 0; r < 8; ++r) vv[r] = fmaf((y[r] - mu) * rs, gg[r], bb[r]);
        *reinterpret_cast<float4*>(&sh_vp[i * VSA_N + t0])     = make_float4(vv[0], vv[1], vv[2], vv[3]);
        *reinterpret_cast<float4*>(&sh_vp[i * VSA_N + t0 + 4]) = make_float4(vv[4], vv[5], vv[6], vv[7]);
    }
    GBAR();   // all vp rows of this group visible

    // ---- scores: neg-count via sign-bit XOR (strided t = wg_tid + 128*r) ----
    int neg[25];
    #pragma unroll
    for (int q = 0; q < 25; ++q) neg[q] = 0;
    #pragma unroll 1
    for (int r = 0; r < 8; ++r) {
        const int t = wg_tid + (r << 7);
        float vpv[5]; int vpb[5]; float spv[5];
        #pragma unroll
        for (int i = 0; i < 5; ++i) {
            vpv[i] = sh_vp[i * VSA_N + t];
            vpb[i] = __float_as_int(vpv[i]);
        }
        #pragma unroll
        for (int j = 0; j < 5; ++j) spv[j] = g_sp[j * VSA_N + t];
        #pragma unroll
        for (int j = 0; j < 5; ++j) {
            #pragma unroll
            for (int i = 0; i < 5; ++i) {
                float c = vpv[i] + spv[j];
                neg[j * 5 + i] += (int)(((unsigned)(vpb[i] ^ __float_as_int(c))) >> 31);
            }
        }
    }
    #pragma unroll
    for (int q = 0; q < 25; ++q) neg[q] = __reduce_add_sync(0xffffffffu, neg[q]);
    if (lane == 0) {
        #pragma unroll
        for (int q = 0; q < 25; ++q) sh_negw[warp * 25 + q] = neg[q];
    }
    GBAR();
    if (wg_tid < 25) {
        int tot = sh_negw[wg_tid] + sh_negw[25 + wg_tid] + sh_negw[50 + wg_tid] + sh_negw[75 + wg_tid];
        sh_w[wg_tid] = (float)(VSA_N - 2 * tot) * (1.f / VSA_N);
    }
    GBAR();
    if (wg_tid < 5) {   // softmax over i for row j = wg_tid
        float s[5];
        #pragma unroll
        for (int i = 0; i < 5; ++i) s[i] = sh_w[wg_tid * 5 + i];
        float m = s[0];
        #pragma unroll
        for (int i = 1; i < 5; ++i) m = fmaxf(m, s[i]);
        float e[5]; float sum = 0.f;
        #pragma unroll
        for (int i = 0; i < 5; ++i) { e[i] = __expf(s[i] - m); sum += e[i]; }
        float inv = 1.f / sum;
        #pragma unroll
        for (int i = 0; i < 5; ++i) sh_w[wg_tid * 5 + i] = e[i] * inv;
    }
    GBAR();

    // ---- att + final silu + store (strided t, coalesced) ----
    float wloc[25];
    #pragma unroll
    for (int q = 0; q < 25; ++q) wloc[q] = sh_w[q];
    const int ob = b * (S_N * VSA_N);
    #pragma unroll 1
    for (int r = 0; r < 8; ++r) {
        const int t = wg_tid + (r << 7);
        float vpv[5], spv[5];
        #pragma unroll
        for (int i = 0; i < 5; ++i) vpv[i] = sh_vp[i * VSA_N + t];
        #pragma unroll
        for (int j = 0; j < 5; ++j) spv[j] = g_sp[j * VSA_N + t];
        #pragma unroll
        for (int j = 0; j < 5; ++j) {
            float a = 0.f;
            #pragma unroll
            for (int i = 0; i < 5; ++i) a = fmaf(wloc[j * 5 + i], vpv[i], a);
            out[ob + j * VSA_N + t] = fast_silu(a * spv[j]);
        }
    }
}

extern "C" void kernel_launch(void* const* d_in, const int* in_sizes, int n_in,
                              void* d_out, int out_size) {
    (void)in_sizes; (void)n_in; (void)out_size;
    const float* values  = (const float*)d_in[0];
    const float* h       = (const float*)d_in[1];
    const float* symbols = (const float*)d_in[2];
    const float* gamma   = (const float*)d_in[3];
    const float* beta    = (const float*)d_in[4];
    float* out = (float*)d_out;

    static int attr_set = 0;
    if (!attr_set) {
        cudaFuncSetAttribute(fused_main, cudaFuncAttributeMaxDynamicSharedMemorySize, SMEM_DYN);
        attr_set = 1;
    }

    sp_kernel<<<S_N, 128>>>(h, symbols, gamma, beta);
    fused_main<<<B_N / GROUPS, TPB, SMEM_DYN>>>(values, gamma, beta, out);
}

// round 16
// speedup vs baseline: 1.7924x; 1.7924x over previous
#include <cuda_runtime.h>

#define B_N   4096
#define S_N   5
#define D_N   64
#define HS_N  961
#define VSA_N 1024
#define LN_EPSF 1e-3f
#define KPAD 72
#define KTOT 1096   // 8 * 137
#define MDIM 137

#define GROUPS 4
#define TPB    512

// dynamic smem layout (bytes)
#define OFF_HS   0                       // float[5480]          = 21920 (shared)
#define OFF_XD   21920                   // ull[4][320]          = 10240
#define OFF_VP   32160                   // float[4][5120]       = 81920
#define OFF_AUX  114080                  // 4 * 352
#define AUX_STRIDE 352
#define SMEM_DYN (OFF_AUX + GROUPS * AUX_STRIDE)   // 115488 -> 2 CTAs/SM

typedef unsigned long long ull;

__device__ float g_sp[S_N * VSA_N];               // batch-invariant sp rows
__device__ __align__(16) float g_hs[S_N * KTOT];  // prebuilt strided padded h (R2/R12 layout)

// ---- packed f32x2 primitives (sm_103a) ----
#define PACK2(dst, lo, hi) \
    asm("mov.b64 %0, {%1, %2};" : "=l"(dst) : "f"(lo), "f"(hi))
#define FMA2(acc, a, b) \
    asm("fma.rn.f32x2 %0, %1, %2, %0;" : "+l"(acc) : "l"(a), "l"(b))
#define UNPACK2(lo, hi, src) \
    asm("mov.b64 {%0, %1}, %2;" : "=f"(lo), "=f"(hi) : "l"(src))

// group barrier: 128 threads of group g, named barrier id g+1
#define GBAR() asm volatile("bar.sync %0, %1;" :: "r"(g + 1), "r"(128) : "memory")

__device__ __forceinline__ float fast_silu(float x) {
    return x / (1.0f + __expf(-x));
}

// conv for 8 consecutive outputs t0..t0+7 (t0 = 8*tid_in_group).
// h path/ring/FMA order VERBATIM R12; the only diff: x arrives pre-duplicated
// (px[d] = (x_d, x_d)) via broadcast LDS.64 instead of float4-load + PACK2.
__device__ __forceinline__ void conv_row2(const float* __restrict__ hsi,
                                          const ull* __restrict__ px,
                                          int t0, float acc[8]) {
    unsigned long long acc2[4] = {0ull, 0ull, 0ull, 0ull};
    unsigned long long pw[8];
    const float* hp = hsi + ((1032 - t0) >> 3);
    float lprev;
    {   // prime: l_{-7}..l_{-1}; packs pw_{-6}..pw_{-1} -> slots 2..7
        float lp[7];
        #pragma unroll
        for (int j = 0; j < 7; ++j) {
            const int d = j - 7;
            lp[j] = hp[(d & 7) * MDIM + (d >> 3)];
        }
        #pragma unroll
        for (int j = 1; j < 7; ++j) {
            const int d = j - 7;
            PACK2(pw[d & 7], lp[j - 1], lp[j]);
        }
        lprev = lp[6];
    }
    const float* hq = hp;
    #pragma unroll 2
    for (int c = 0; c < 8; ++c) {
        float ln[8];
        #pragma unroll
        for (int s = 0; s < 8; ++s) ln[s] = hq[s * MDIM];   // 8 independent LDS.32
        #pragma unroll
        for (int s = 0; s < 8; ++s) {
            float pv = (s == 0) ? lprev : ln[s - 1];
            PACK2(pw[s & 7], pv, ln[s]);                    // pw_d = (l_{d-1}, l_d)
            ull xx = px[(c << 3) + s];                      // broadcast LDS.64: (x_d, x_d)
            FMA2(acc2[0], xx, pw[s & 7]);                   // acc[1],acc[0]
            FMA2(acc2[1], xx, pw[(s + 6) & 7]);             // acc[3],acc[2]
            FMA2(acc2[2], xx, pw[(s + 4) & 7]);             // acc[5],acc[4]
            FMA2(acc2[3], xx, pw[(s + 2) & 7]);             // acc[7],acc[6]
        }
        lprev = ln[7];
        hq += 1;
    }
    #pragma unroll
    for (int p = 0; p < 4; ++p) UNPACK2(acc[2 * p + 1], acc[2 * p], acc2[p]);
}

// ---------------- kernel 0: build g_hs + sp rows (one block per i) ----------------
__global__ __launch_bounds__(128)
void sp_kernel(const float* __restrict__ h,
               const float* __restrict__ symbols,
               const float* __restrict__ gamma,
               const float* __restrict__ beta) {
    __shared__ __align__(16) float sh_hs[KTOT];
    __shared__ __align__(16) ull sh_xd[D_N];
    __shared__ float sh_red[8];
    __shared__ float sh_stats[2];

    const int tid  = threadIdx.x;
    const int lane = tid & 31;
    const int warp = tid >> 5;
    const int i    = blockIdx.x;

    for (int K = tid; K < KTOT; K += 128) {
        const int k = K - KPAD;
        const float v = (k >= 0 && k < HS_N) ? h[i * HS_N + k] : 0.f;
        const int a = (K & 7) * MDIM + (K >> 3);
        sh_hs[a] = v;
        g_hs[i * KTOT + a] = v;
    }
    if (tid < D_N) {
        unsigned u = __float_as_uint(symbols[i * D_N + tid]);
        sh_xd[tid] = ((ull)u << 32) | (ull)u;
    }
    __syncthreads();

    const int t0 = tid << 3;
    float acc[8];
    conv_row2(sh_hs, sh_xd, t0, acc);

    float y[8];
    float s1 = 0.f, s2 = 0.f;
    #pragma unroll
    for (int r = 0; r < 8; ++r) {
        float u = fast_silu(acc[r]);
        y[r] = u; s1 += u; s2 += u * u;
    }
    #pragma unroll
    for (int o = 16; o > 0; o >>= 1) {
        s1 += __shfl_xor_sync(0xffffffffu, s1, o);
        s2 += __shfl_xor_sync(0xffffffffu, s2, o);
    }
    if (lane == 0) { sh_red[warp] = s1; sh_red[4 + warp] = s2; }
    __syncthreads();
    if (tid == 0) {
        float a = sh_red[0] + sh_red[1] + sh_red[2] + sh_red[3];
        float q = sh_red[4] + sh_red[5] + sh_red[6] + sh_red[7];
        float mu = a * (1.f / VSA_N);
        float var = q * (1.f / VSA_N) - mu * mu;
        sh_stats[0] = mu;
        sh_stats[1] = rsqrtf(var + LN_EPSF);
    }
    __syncthreads();
    float mu = sh_stats[0], rs = sh_stats[1];
    #pragma unroll
    for (int r = 0; r < 8; ++r) {
        const int t = t0 + r;
        g_sp[i * VSA_N + t] = fmaf((y[r] - mu) * rs, gamma[t], beta[t]);
    }
}

// ---------------- main fused kernel: 4 batch groups per 512-thread block ----------------
__global__ __launch_bounds__(TPB, 2)
void fused_main(const float* __restrict__ values,
                const float* __restrict__ gamma,
                const float* __restrict__ beta,
                float* __restrict__ out) {
    extern __shared__ __align__(16) char dynsm[];

    const int tid    = threadIdx.x;
    const int g      = tid >> 7;          // group 0..3
    const int wg_tid = tid & 127;         // tid within group
    const int lane   = tid & 31;
    const int warp   = (tid >> 5) & 3;    // warp within group
    const int b      = blockIdx.x * GROUPS + g;
    const int t0     = wg_tid << 3;

    float* sh_hs    = (float*)(dynsm + OFF_HS);                       // shared by all groups
    ull*   sh_xd    = (ull*)(dynsm + OFF_XD) + g * (S_N * D_N);
    float* sh_vp    = (float*)(dynsm + OFF_VP) + g * (S_N * VSA_N);
    char*  auxp     = dynsm + OFF_AUX + g * AUX_STRIDE;
    short* sh_negw  = (short*)auxp;            // [0,200)  short[4][25]
    float* sh_red   = (float*)(auxp + 200);    // [200,232)
    float* sh_stats = (float*)(auxp + 232);    // [232,240)
    float* sh_w     = (float*)(auxp + 240);    // [240,340)

    // cooperative h-table load (all 512 threads)
    {
        const float4* src = reinterpret_cast<const float4*>(g_hs);
        float4* dst = reinterpret_cast<float4*>(sh_hs);
        #pragma unroll 1
        for (int idx = tid; idx < (S_N * KTOT) / 4; idx += TPB) dst[idx] = src[idx];
    }
    // per-group x dup pairs from global values
    {
        const float* vb = values + (size_t)b * (S_N * D_N);
        #pragma unroll 1
        for (int idx = wg_tid; idx < S_N * D_N; idx += 128) {
            unsigned u = __float_as_uint(vb[idx]);
            sh_xd[idx] = ((ull)u << 32) | (ull)u;
        }
    }
    __syncthreads();   // only block-wide barrier; groups independent after this

    // ---- conv + silu + LayerNorm per i -> sh_vp ----
    #pragma unroll 1
    for (int i = 0; i < S_N; ++i) {
        float acc[8];
        conv_row2(sh_hs + i * KTOT, sh_xd + i * D_N, t0, acc);

        float y[8];
        float s1 = 0.f, s2 = 0.f;
        #pragma unroll
        for (int r = 0; r < 8; ++r) {
            float u = fast_silu(acc[r]);
            y[r] = u; s1 += u; s2 += u * u;
        }
        #pragma unroll
        for (int o = 16; o > 0; o >>= 1) {
            s1 += __shfl_xor_sync(0xffffffffu, s1, o);
            s2 += __shfl_xor_sync(0xffffffffu, s2, o);
        }
        if (lane == 0) { sh_red[warp] = s1; sh_red[4 + warp] = s2; }
        GBAR();
        if (wg_tid == 0) {
            float a = sh_red[0] + sh_red[1] + sh_red[2] + sh_red[3];
            float q = sh_red[4] + sh_red[5] + sh_red[6] + sh_red[7];
            float mu = a * (1.f / VSA_N);
            float var = q * (1.f / VSA_N) - mu * mu;
            sh_stats[0] = mu;
            sh_stats[1] = rsqrtf(var + LN_EPSF);
        }
        GBAR();
        float mu = sh_stats[0], rs = sh_stats[1];

        float4 g0  = *reinterpret_cast<const float4*>(gamma + t0);
        float4 g1  = *reinterpret_cast<const float4*>(gamma + t0 + 4);
        float4 be0 = *reinterpret_cast<const float4*>(beta + t0);
        float4 be1 = *reinterpret_cast<const float4*>(beta + t0 + 4);
        float gg[8] = {g0.x, g0.y, g0.z, g0.w, g1.x, g1.y, g1.z, g1.w};
        float bb[8] = {be0.x, be0.y, be0.z, be0.w, be1.x, be1.y, be1.z, be1.w};
        float vv[8];
        #pragma unroll
        for (int r = 0; r < 8; ++r) vv[r] = fmaf((y[r] - mu) * rs, gg[r], bb[r]);
        *reinterpret_cast<float4*>(&sh_vp[i * VSA_N + t0])     = make_float4(vv[0], vv[1], vv[2], vv[3]);
        *reinterpret_cast<float4*>(&sh_vp[i * VSA_N + t0 + 4]) = make_float4(vv[4], vv[5], vv[6], vv[7]);
    }
    GBAR();   // all vp rows of this group visible

    // ---- scores: neg-count via sign-bit XOR (strided t = wg_tid + 128*r) ----
    int neg[25];
    #pragma unroll
    for (int q = 0; q < 25; ++q) neg[q] = 0;
    #pragma unroll 1
    for (int r = 0; r < 8; ++r) {
        const int t = wg_tid + (r << 7);
        float vpv[5]; int vpb[5]; float spv[5];
        #pragma unroll
        for (int i = 0; i < 5; ++i) {
            vpv[i] = sh_vp[i * VSA_N + t];
            vpb[i] = __float_as_int(vpv[i]);
        }
        #pragma unroll
        for (int j = 0; j < 5; ++j) spv[j] = g_sp[j * VSA_N + t];
        #pragma unroll
        for (int j = 0; j < 5; ++j) {
            #pragma unroll
            for (int i = 0; i < 5; ++i) {
                float c = vpv[i] + spv[j];
                neg[j * 5 + i] += (int)(((unsigned)(vpb[i] ^ __float_as_int(c))) >> 31);
            }
        }
    }
    #pragma unroll
    for (int q = 0; q < 25; ++q) neg[q] = __reduce_add_sync(0xffffffffu, neg[q]);
    if (lane == 0) {
        #pragma unroll
        for (int q = 0; q < 25; ++q) sh_negw[warp * 25 + q] = (short)neg[q];
    }
    GBAR();
    if (wg_tid < 25) {
        int tot = (int)sh_negw[wg_tid] + (int)sh_negw[25 + wg_tid]
                + (int)sh_negw[50 + wg_tid] + (int)sh_negw[75 + wg_tid];
        sh_w[wg_tid] = (float)(VSA_N - 2 * tot) * (1.f / VSA_N);
    }
    GBAR();
    if (wg_tid < 5) {   // softmax over i for row j = wg_tid
        float s[5];
        #pragma unroll
        for (int i = 0; i < 5; ++i) s[i] = sh_w[wg_tid * 5 + i];
        float m = s[0];
        #pragma unroll
        for (int i = 1; i < 5; ++i) m = fmaxf(m, s[i]);
        float e[5]; float sum = 0.f;
        #pragma unroll
        for (int i = 0; i < 5; ++i) { e[i] = __expf(s[i] - m); sum += e[i]; }
        float inv = 1.f / sum;
        #pragma unroll
        for (int i = 0; i < 5; ++i) sh_w[wg_tid * 5 + i] = e[i] * inv;
    }
    GBAR();

    // ---- att + final silu + store (strided t, coalesced) ----
    float wloc[25];
    #pragma unroll
    for (int q = 0; q < 25; ++q) wloc[q] = sh_w[q];
    const int ob = b * (S_N * VSA_N);
    #pragma unroll 1
    for (int r = 0; r < 8; ++r) {
        const int t = wg_tid + (r << 7);
        float vpv[5], spv[5];
        #pragma unroll
        for (int i = 0; i < 5; ++i) vpv[i] = sh_vp[i * VSA_N + t];
        #pragma unroll
        for (int j = 0; j < 5; ++j) spv[j] = g_sp[j * VSA_N + t];
        #pragma unroll
        for (int j = 0; j < 5; ++j) {
            float a = 0.f;
            #pragma unroll
            for (int i = 0; i < 5; ++i) a = fmaf(wloc[j * 5 + i], vpv[i], a);
            out[ob + j * VSA_N + t] = fast_silu(a * spv[j]);
        }
    }
}

extern "C" void kernel_launch(void* const* d_in, const int* in_sizes, int n_in,
                              void* d_out, int out_size) {
    (void)in_sizes; (void)n_in; (void)out_size;
    const float* values  = (const float*)d_in[0];
    const float* h       = (const float*)d_in[1];
    const float* symbols = (const float*)d_in[2];
    const float* gamma   = (const float*)d_in[3];
    const float* beta    = (const float*)d_in[4];
    float* out = (float*)d_out;

    static int attr_set = 0;
    if (!attr_set) {
        cudaFuncSetAttribute(fused_main, cudaFuncAttributeMaxDynamicSharedMemorySize, SMEM_DYN);
        attr_set = 1;
    }

    sp_kernel<<<S_N, 128>>>(h, symbols, gamma, beta);
    fused_main<<<B_N / GROUPS, TPB, SMEM_DYN>>>(values, gamma, beta, out);
}